// round 13
// baseline (speedup 1.0000x reference)
#include <cuda_runtime.h>
#include <cuda_fp16.h>
#include <cstdint>
#include <math_constants.h>

#define NSTEPS 512
#define KDIM   513
#define BATCH  65536
#define COLS   512
#define NSEG   8           // 8 segments x 64 steps
#define NQUAD  128         // 4-step quads
#define RPG    32          // rows per group
#define NGRP   4           // groups per block
#define RPB    (RPG*NGRP)  // 128 rows per block
#define NTHR   512

#define PREP_T4_BLOCKS 256 // 128 quads x 2 p-chunks of 256
#define PREP_TOTAL     257 // + endW block (<= 2*148 resident -> no deadlock)

// Persistent tables (~2 MB) + barrier state.
__device__ __half g_T4[NQUAD * COLS * 16];  // fused 4-step log table (fp16)
__device__ float  g_logE[KDIM];
__device__ int    g_done;                   // prep completion counter
__device__ int    g_fin;                    // block completion counter

// ---------------------------------------------------------------------------
// Single fused kernel with warp-specialized pack/walk pipeline.
//   Phase 0 (blocks <257): build T4 / logE (all resident in wave 1).
//   Pipeline (all blocks): 4 groups of 32 rows, double-buffered in smem.
//     it=0..4: warps 0-7 pack group it | warps 8-15 walk group it-1.
//     -> DRAM streaming and L2 gathers run CONCURRENTLY on every SM.
// ---------------------------------------------------------------------------
__global__ void __launch_bounds__(NTHR, 2) mega_kernel(
        const int* __restrict__ x, const float* __restrict__ W,
        const float* __restrict__ endW, float* __restrict__ out) {
    __shared__ float        ls[4][260][2];          // prep softmax window
    __shared__ unsigned int s_words[2][RPG][17];    // double-buffered bits
    __shared__ int          s_ps[2][RPG][9];        // double-buffered prefixes
    __shared__ float        s_part[2][NSEG][RPG];   // double-buffered partials

    const unsigned F = 0xffffffffu;
    int tid  = threadIdx.x;
    int w    = tid >> 5;
    int lane = tid & 31;
    int bid  = blockIdx.x;
    int r0   = bid * RPB;

    // ---- Phase 0: table prep on the first 257 blocks ----
    if (bid < PREP_T4_BLOCKS) {
        int i     = bid >> 1;              // quad index [0,128)
        int pbase = (bid & 1) << 8;        // 256-wide p-chunk

        for (int idx = tid; idx < 4 * 260; idx += NTHR) {
            int k  = idx / 260;
            int jj = idx - k * 260;
            int t  = 4 * i + k;
            int j  = pbase - 1 + jj;
            float l0 = 0.f, l1 = 0.f;
            if (j >= 0 && j <= t - 1) {
                float w0 = W[((size_t)(t - 1) * COLS + j) * 2 + 0];
                float w1 = W[((size_t)(t - 1) * COLS + j) * 2 + 1];
                float m  = fmaxf(w0, w1);
                float lse = m + __logf(1.f + __expf(-fabsf(w0 - w1)));
                l0 = w0 - lse;
                l1 = w1 - lse;
            }
            ls[k][jj][0] = l0;
            ls[k][jj][1] = l1;
        }
        __syncthreads();

        int p    = pbase + (tid >> 1);
        int cgrp = (tid & 1) * 8;
        __align__(16) __half2 hv[4];
        #pragma unroll
        for (int cp = 0; cp < 4; ++cp) {
            float v2[2];
            #pragma unroll
            for (int lo = 0; lo < 2; ++lo) {
                int c = cgrp + cp * 2 + lo;
                int q = p;
                float v = 0.f;
                #pragma unroll
                for (int k = 0; k < 4; ++k) {
                    int b  = (c >> k) & 1;
                    int qn = q + b;
                    int t  = 4 * i + k;
                    if (qn >= 1 && qn <= t) v += ls[k][qn - pbase][b];
                    q = qn;
                }
                v2[lo] = v;
            }
            hv[cp] = __floats2half2_rn(v2[0], v2[1]);
        }
        *reinterpret_cast<uint4*>(&g_T4[(((size_t)i * COLS + p) * 16) + cgrp]) =
            *reinterpret_cast<const uint4*>(hv);

        __syncthreads();
        __threadfence();
        if (tid == 0) atomicAdd(&g_done, 1);
    } else if (bid == PREP_T4_BLOCKS) {
        if (tid < 32) {
            float m = -CUDART_INF_F;
            for (int k = tid; k < KDIM; k += 32) m = fmaxf(m, endW[k]);
            #pragma unroll
            for (int o = 16; o; o >>= 1) m = fmaxf(m, __shfl_xor_sync(F, m, o));
            float s = 0.f;
            for (int k = tid; k < KDIM; k += 32) s += __expf(endW[k] - m);
            #pragma unroll
            for (int o = 16; o; o >>= 1) s += __shfl_xor_sync(F, s, o);
            float lse = m + __logf(s);
            for (int k = tid; k < KDIM; k += 32) g_logE[k] = endW[k] - lse;
        }
        __syncthreads();
        __threadfence();
        if (tid == 0) atomicAdd(&g_done, 1);
    }

    // ---- Pipeline: pack warps (0-7) / walk warps (8-15), double buffer ----
    bool is_pack = (w < 8);
    int  seg     = w - 8;

    #pragma unroll 1
    for (int it = 0; it <= NGRP; ++it) {
        if (is_pack) {
            if (it < NGRP) {
                int buf = it & 1;
                #pragma unroll 1
                for (int i = 0; i < 4; ++i) {
                    int row_local = w * 4 + i;
                    const int4* __restrict__ xr = (const int4*)
                        (x + (size_t)(r0 + it * RPG + row_local) * NSTEPS);

                    unsigned int words[4];
                    int hv[8];
                    #pragma unroll
                    for (int itr = 0; itr < 4; ++itr) {
                        int4 v = xr[itr * 32 + lane];
                        unsigned int nib = (unsigned)(v.x != 0)
                                         | ((unsigned)(v.y != 0) << 1)
                                         | ((unsigned)(v.z != 0) << 2)
                                         | ((unsigned)(v.w != 0) << 3);
                        unsigned int part = nib << ((lane & 7) * 4);
                        part |= __shfl_xor_sync(F, part, 1);
                        part |= __shfl_xor_sync(F, part, 2);
                        part |= __shfl_xor_sync(F, part, 4);
                        words[itr] = part;

                        int pc = __popc(nib);   // xor 1,2,4,8 stays in 16 lanes
                        pc += __shfl_xor_sync(F, pc, 1);
                        pc += __shfl_xor_sync(F, pc, 2);
                        pc += __shfl_xor_sync(F, pc, 4);
                        pc += __shfl_xor_sync(F, pc, 8);
                        hv[itr * 2 + 0] = __shfl_sync(F, pc, 0);
                        hv[itr * 2 + 1] = __shfl_sync(F, pc, 16);
                    }
                    if ((lane & 7) == 0) {
                        int g = lane >> 3;
                        #pragma unroll
                        for (int itr = 0; itr < 4; ++itr)
                            s_words[buf][row_local][itr * 4 + g] = words[itr];
                    }
                    if (lane < NSEG) {
                        int ps = 0;
                        #pragma unroll
                        for (int j = 0; j < NSEG - 1; ++j)
                            if (j < lane) ps += hv[j];
                        s_ps[buf][row_local][lane] = ps;
                    }
                }
            }
        } else if (it >= 1) {
            int buf = (it - 1) & 1;
            int p = s_ps[buf][lane][seg];
            uint64_t word = (uint64_t)s_words[buf][lane][2 * seg + 0]
                          | ((uint64_t)s_words[buf][lane][2 * seg + 1] << 32);

            const __half* __restrict__ T = g_T4 + (size_t)(seg * 16) * 8192;
            unsigned hq = (unsigned)p << 4;
            float acc0 = 0.f, acc1 = 0.f;

            #pragma unroll
            for (int k = 0; k < 16; ++k) {
                unsigned c = (unsigned)(word >> (4 * k)) & 15u;
                float v = __half2float(__ldg(&T[k * 8192 + (hq | c)]));
                if (k & 1) acc1 += v; else acc0 += v;
                hq += (unsigned)__popc(c) << 4;
            }

            float acc = acc0 + acc1;
            if (seg == NSEG - 1) acc += g_logE[hq >> 4];
            s_part[buf][seg][lane] = acc;
        }
        __syncthreads();

        // After the first stage: wait for the table before any walk starts.
        if (it == 0) {
            if (tid == 0) {
                while (atomicAdd(&g_done, 0) < PREP_TOTAL) __nanosleep(64);
            }
            __syncthreads();
            __threadfence();
        }

        // Reduce finished group (warp 0; completes before next sync, and the
        // buffer it reads is next overwritten only after that sync).
        if (it >= 1 && w == 0) {
            int buf = (it - 1) & 1;
            float s = 0.f;
            #pragma unroll
            for (int j = 0; j < NSEG; ++j) s += s_part[buf][j][lane];
            out[r0 + (it - 1) * RPG + lane] = s;
        }
    }

    // ---- Reset barrier state for the next graph replay (deterministic) ----
    if (tid == 0) {
        int f = atomicAdd(&g_fin, 1);
        if (f == (int)gridDim.x - 1) {
            g_done = 0;
            __threadfence();
            g_fin = 0;
        }
    }
}

// ---------------------------------------------------------------------------
extern "C" void kernel_launch(void* const* d_in, const int* in_sizes, int n_in,
                              void* d_out, int out_size) {
    const int*   x    = (const int*)  d_in[0];   // (65536, 512) int32
    const float* W    = (const float*)d_in[1];   // (511, 512, 2) float32
    const float* endW = (const float*)d_in[2];   // (1, 513) float32
    float* out = (float*)d_out;

    (void)in_sizes; (void)n_in; (void)out_size;

    mega_kernel<<<BATCH / RPB, NTHR>>>(x, W, endW, out);
}

// round 14
// speedup vs baseline: 1.4753x; 1.4753x over previous
#include <cuda_runtime.h>
#include <cuda_fp16.h>
#include <cstdint>
#include <math_constants.h>

#define NSTEPS 512
#define KDIM   513
#define BATCH  65536
#define COLS   512
#define NSEG   8           // 8 segments x 64 steps
#define NQUAD  128         // 4-step quads
#define RPB    32          // rows per block

#define PREP_T4_BLOCKS 512 // 128 quads x 4 p-chunks of 128
#define PREP_TOTAL     513 // + endW block

// Persistent tables (~2 MB) + barrier state.
__device__ __half g_T4[NQUAD * COLS * 16];  // fused 4-step log table (fp16)
__device__ float  g_logE[KDIM];
__device__ int    g_done;                   // prep completion counter
__device__ int    g_fin;                    // block completion counter

// ---------------------------------------------------------------------------
// Single fused kernel (R9 structure). The prep combo path is written with
// minimal live state (compute one half2, store it immediately) so the WHOLE
// kernel's register allocation stays near the walk's natural ~36-40 regs --
// the walk phase is what needs occupancy and 16-deep LDG batching.
// launch_bounds(256,4) is only the deadlock guarantee: >=592 resident blocks
// >= 513 prep blocks, so the g_done wait cannot hang.
// ---------------------------------------------------------------------------
__global__ void __launch_bounds__(256, 4) mega_kernel(
        const int* __restrict__ x, const float* __restrict__ W,
        const float* __restrict__ endW, float* __restrict__ out) {
    __shared__ float        ls[4][132][2];     // prep softmax window
    __shared__ unsigned int s_words[RPB][17];
    __shared__ int          s_ps[RPB][9];
    __shared__ float        s_part[NSEG][RPB];

    const unsigned F = 0xffffffffu;
    int tid  = threadIdx.x;
    int w    = tid >> 5;
    int lane = tid & 31;
    int bid  = blockIdx.x;
    int r0   = bid * RPB;

    // ---- Phase 0: table prep on the first 513 blocks ----
    if (bid < PREP_T4_BLOCKS) {
        int i     = bid >> 2;              // quad index [0,128)
        int pbase = (bid & 3) << 7;        // 128-wide p-chunk

        // ls[k][jj][b] = log-softmax of W[4i+k-1][pbase-1+jj][b] (0 outside)
        for (int idx = tid; idx < 4 * 132; idx += 256) {
            int k  = idx / 132;
            int jj = idx - k * 132;
            int t  = 4 * i + k;
            int j  = pbase - 1 + jj;
            float l0 = 0.f, l1 = 0.f;
            if (j >= 0 && j <= t - 1) {
                float w0 = W[((size_t)(t - 1) * COLS + j) * 2 + 0];
                float w1 = W[((size_t)(t - 1) * COLS + j) * 2 + 1];
                float m  = fmaxf(w0, w1);
                float lse = m + __logf(1.f + __expf(-fabsf(w0 - w1)));
                l0 = w0 - lse;
                l1 = w1 - lse;
            }
            ls[k][jj][0] = l0;
            ls[k][jj][1] = l1;
        }
        __syncthreads();

        // Each thread: one p, 8 combos. One half2 computed and stored at a
        // time (4-B store) -> minimal live registers in this path.
        int p    = pbase + (tid >> 1);
        int cgrp = (tid & 1) * 8;
        __half* dst = &g_T4[(((size_t)i * COLS + p) * 16) + cgrp];
        #pragma unroll 1
        for (int cp = 0; cp < 4; ++cp) {
            float v2[2];
            #pragma unroll
            for (int lo = 0; lo < 2; ++lo) {
                int c = cgrp + cp * 2 + lo;
                int q = p;
                float v = 0.f;
                #pragma unroll
                for (int k = 0; k < 4; ++k) {
                    int b  = (c >> k) & 1;
                    int qn = q + b;
                    int t  = 4 * i + k;
                    if (qn >= 1 && qn <= t) v += ls[k][qn - pbase][b];
                    q = qn;
                }
                v2[lo] = v;
            }
            *reinterpret_cast<__half2*>(dst + cp * 2) =
                __floats2half2_rn(v2[0], v2[1]);
        }

        __syncthreads();
        __threadfence();
        if (tid == 0) atomicAdd(&g_done, 1);
    } else if (bid == PREP_T4_BLOCKS) {
        if (tid < 32) {
            float m = -CUDART_INF_F;
            for (int k = tid; k < KDIM; k += 32) m = fmaxf(m, endW[k]);
            #pragma unroll
            for (int o = 16; o; o >>= 1) m = fmaxf(m, __shfl_xor_sync(F, m, o));
            float s = 0.f;
            for (int k = tid; k < KDIM; k += 32) s += __expf(endW[k] - m);
            #pragma unroll
            for (int o = 16; o; o >>= 1) s += __shfl_xor_sync(F, s, o);
            float lse = m + __logf(s);
            for (int k = tid; k < KDIM; k += 32) g_logE[k] = endW[k] - lse;
        }
        __syncthreads();
        __threadfence();
        if (tid == 0) atomicAdd(&g_done, 1);
    }

    // ---- Phase 1: pack (independent of T4) ----
    #pragma unroll 1
    for (int i = 0; i < 4; ++i) {
        int row_local = w * 4 + i;
        const int4* __restrict__ xr =
            (const int4*)(x + (size_t)(r0 + row_local) * NSTEPS);

        unsigned int words[4];
        int hv[8];
        #pragma unroll
        for (int it = 0; it < 4; ++it) {
            int4 v = xr[it * 32 + lane];
            unsigned int nib = (unsigned)(v.x != 0)
                             | ((unsigned)(v.y != 0) << 1)
                             | ((unsigned)(v.z != 0) << 2)
                             | ((unsigned)(v.w != 0) << 3);
            unsigned int part = nib << ((lane & 7) * 4);
            part |= __shfl_xor_sync(F, part, 1);
            part |= __shfl_xor_sync(F, part, 2);
            part |= __shfl_xor_sync(F, part, 4);
            words[it] = part;

            int pc = __popc(nib);            // xor 1,2,4,8 stays in 16 lanes
            pc += __shfl_xor_sync(F, pc, 1);
            pc += __shfl_xor_sync(F, pc, 2);
            pc += __shfl_xor_sync(F, pc, 4);
            pc += __shfl_xor_sync(F, pc, 8);
            hv[it * 2 + 0] = __shfl_sync(F, pc, 0);
            hv[it * 2 + 1] = __shfl_sync(F, pc, 16);
        }
        if ((lane & 7) == 0) {
            int g = lane >> 3;
            #pragma unroll
            for (int it = 0; it < 4; ++it)
                s_words[row_local][it * 4 + g] = words[it];
        }
        if (lane < NSEG) {
            int ps = 0;
            #pragma unroll
            for (int j = 0; j < NSEG - 1; ++j) if (j < lane) ps += hv[j];
            s_ps[row_local][lane] = ps;
        }
    }
    __syncthreads();

    // ---- Barrier: wait for table completion ----
    if (tid == 0) {
        while (atomicAdd(&g_done, 0) < PREP_TOTAL) __nanosleep(64);
    }
    __syncthreads();
    __threadfence();

    // ---- Phase 2: walk. seg = w, row = lane. 16 quad-gathers ----
    int p = s_ps[lane][w];
    uint64_t word = (uint64_t)s_words[lane][2 * w + 0]
                  | ((uint64_t)s_words[lane][2 * w + 1] << 32);

    const __half* __restrict__ T = g_T4 + (size_t)(w * 16) * 8192;
    unsigned hq = (unsigned)p << 4;          // running index, multiple of 16
    float acc0 = 0.f, acc1 = 0.f;

    #pragma unroll
    for (int k = 0; k < 16; ++k) {
        unsigned c = (unsigned)(word >> (4 * k)) & 15u;
        float v = __half2float(__ldg(&T[k * 8192 + (hq | c)]));
        if (k & 1) acc1 += v; else acc0 += v;
        hq += (unsigned)__popc(c) << 4;
    }

    float acc = acc0 + acc1;
    if (w == NSEG - 1) acc += g_logE[hq >> 4];   // total popcount
    s_part[w][lane] = acc;
    __syncthreads();

    // ---- Phase 3: fixed-order reduce ----
    if (w == 0) {
        float s = 0.f;
        #pragma unroll
        for (int j = 0; j < NSEG; ++j) s += s_part[j][lane];
        out[r0 + lane] = s;
    }

    // ---- Reset barrier state for the next graph replay (deterministic) ----
    if (tid == 0) {
        int f = atomicAdd(&g_fin, 1);
        if (f == (int)gridDim.x - 1) {
            g_done = 0;
            __threadfence();
            g_fin = 0;
        }
    }
}

// ---------------------------------------------------------------------------
extern "C" void kernel_launch(void* const* d_in, const int* in_sizes, int n_in,
                              void* d_out, int out_size) {
    const int*   x    = (const int*)  d_in[0];   // (65536, 512) int32
    const float* W    = (const float*)d_in[1];   // (511, 512, 2) float32
    const float* endW = (const float*)d_in[2];   // (1, 513) float32
    float* out = (float*)d_out;

    (void)in_sizes; (void)n_in; (void)out_size;

    mega_kernel<<<BATCH / RPB, 256>>>(x, W, endW, out);
}

// round 15
// speedup vs baseline: 1.5444x; 1.0468x over previous
#include <cuda_runtime.h>
#include <cuda_fp16.h>
#include <cstdint>
#include <math_constants.h>

#define NSTEPS 512
#define KDIM   513
#define BATCH  65536
#define COLS   512
#define NSEG   8           // 8 segments x 64 steps
#define NQUAD  128         // 4-step quads
#define RPG    32          // rows per group
#define NGRP   2           // groups per block (double buffer)
#define RPB    (RPG*NGRP)  // 64 rows per block
#define NTHR   256

#define PREP_T4_BLOCKS 512 // 128 quads x 4 p-chunks of 128
#define PREP_TOTAL     513 // + endW block

// Persistent tables (~2 MB) + barrier state.
__device__ __half g_T4[NQUAD * COLS * 16];  // fused 4-step log table (fp16)
__device__ float  g_logE[KDIM];
__device__ int    g_done;                   // prep completion counter
__device__ int    g_fin;                    // block completion counter

// ---------------------------------------------------------------------------
// Pack helpers (proven ballot/shuffle scheme, split so loads can be issued
// separately from processing for software pipelining).
// ---------------------------------------------------------------------------
__device__ __forceinline__ void load_row(const int4* __restrict__ xr,
                                         int lane, int4 q[4]) {
    #pragma unroll
    for (int it = 0; it < 4; ++it) q[it] = xr[it * 32 + lane];
}

__device__ __forceinline__ void process_store_row(const int4 q[4], int lane,
        unsigned int* sw_row, int* sps_row) {
    const unsigned F = 0xffffffffu;
    unsigned int words[4];
    int hv[8];
    #pragma unroll
    for (int it = 0; it < 4; ++it) {
        unsigned nib = (unsigned)(q[it].x != 0)
                     | ((unsigned)(q[it].y != 0) << 1)
                     | ((unsigned)(q[it].z != 0) << 2)
                     | ((unsigned)(q[it].w != 0) << 3);
        unsigned part = nib << ((lane & 7) * 4);
        part |= __shfl_xor_sync(F, part, 1);
        part |= __shfl_xor_sync(F, part, 2);
        part |= __shfl_xor_sync(F, part, 4);
        words[it] = part;

        int pc = __popc(nib);                // xor 1,2,4,8 stays in 16 lanes
        pc += __shfl_xor_sync(F, pc, 1);
        pc += __shfl_xor_sync(F, pc, 2);
        pc += __shfl_xor_sync(F, pc, 4);
        pc += __shfl_xor_sync(F, pc, 8);
        hv[it * 2 + 0] = __shfl_sync(F, pc, 0);
        hv[it * 2 + 1] = __shfl_sync(F, pc, 16);
    }
    if ((lane & 7) == 0) {
        int g = lane >> 3;
        #pragma unroll
        for (int it = 0; it < 4; ++it) sw_row[it * 4 + g] = words[it];
    }
    if (lane < NSEG) {
        int ps = 0;
        #pragma unroll
        for (int j = 0; j < NSEG - 1; ++j) if (j < lane) ps += hv[j];
        sps_row[lane] = ps;
    }
}

// ---------------------------------------------------------------------------
// Single fused kernel with per-thread pack/walk software pipelining.
//   prep (blocks <513, zero-skip for all-zero chunks) ->
//   prologue: pack group 0 -> poll table barrier ->
//   iter 0: WALK group 0 while LOADING+PACKING group 1 (interleaved) ->
//   iter 1: walk group 1.
// ---------------------------------------------------------------------------
__global__ void __launch_bounds__(NTHR, 4) mega_kernel(
        const int* __restrict__ x, const float* __restrict__ W,
        const float* __restrict__ endW, float* __restrict__ out) {
    __shared__ float        ls[4][132][2];          // prep softmax window
    __shared__ unsigned int s_words[NGRP][RPG][17]; // double-buffered bits
    __shared__ int          s_ps[NGRP][RPG][9];
    __shared__ float        s_part[NGRP][NSEG][RPG];

    const unsigned F = 0xffffffffu;
    int tid  = threadIdx.x;
    int w    = tid >> 5;
    int lane = tid & 31;
    int bid  = blockIdx.x;
    int r0   = bid * RPB;

    // ---- Phase 0: table prep on the first 513 blocks ----
    if (bid < PREP_T4_BLOCKS) {
        int i     = bid >> 2;              // quad index [0,128)
        int pbase = (bid & 3) << 7;        // 128-wide p-chunk

        if (pbase > 4 * i + 3) {
            // Entire chunk is outside the reachable band -> exact zeros.
            int p    = pbase + (tid >> 1);
            int cgrp = (tid & 1) * 8;
            __half* dst = &g_T4[(((size_t)i * COLS + p) * 16) + cgrp];
            __half2 z = __floats2half2_rn(0.f, 0.f);
            #pragma unroll
            for (int cp = 0; cp < 4; ++cp)
                *reinterpret_cast<__half2*>(dst + cp * 2) = z;
        } else {
            // ls[k][jj][b] = log-softmax of W[4i+k-1][pbase-1+jj][b]
            for (int idx = tid; idx < 4 * 132; idx += NTHR) {
                int k  = idx / 132;
                int jj = idx - k * 132;
                int t  = 4 * i + k;
                int j  = pbase - 1 + jj;
                float l0 = 0.f, l1 = 0.f;
                if (j >= 0 && j <= t - 1) {
                    float w0 = W[((size_t)(t - 1) * COLS + j) * 2 + 0];
                    float w1 = W[((size_t)(t - 1) * COLS + j) * 2 + 1];
                    float m  = fmaxf(w0, w1);
                    float lse = m + __logf(1.f + __expf(-fabsf(w0 - w1)));
                    l0 = w0 - lse;
                    l1 = w1 - lse;
                }
                ls[k][jj][0] = l0;
                ls[k][jj][1] = l1;
            }
            __syncthreads();

            int p    = pbase + (tid >> 1);
            int cgrp = (tid & 1) * 8;
            __half* dst = &g_T4[(((size_t)i * COLS + p) * 16) + cgrp];
            #pragma unroll 1
            for (int cp = 0; cp < 4; ++cp) {
                float v2[2];
                #pragma unroll
                for (int lo = 0; lo < 2; ++lo) {
                    int c = cgrp + cp * 2 + lo;
                    int q = p;
                    float v = 0.f;
                    #pragma unroll
                    for (int k = 0; k < 4; ++k) {
                        int b  = (c >> k) & 1;
                        int qn = q + b;
                        int t  = 4 * i + k;
                        if (qn >= 1 && qn <= t) v += ls[k][qn - pbase][b];
                        q = qn;
                    }
                    v2[lo] = v;
                }
                *reinterpret_cast<__half2*>(dst + cp * 2) =
                    __floats2half2_rn(v2[0], v2[1]);
            }
        }
        __syncthreads();
        __threadfence();
        if (tid == 0) atomicAdd(&g_done, 1);
    } else if (bid == PREP_T4_BLOCKS) {
        if (tid < 32) {
            float m = -CUDART_INF_F;
            for (int k = tid; k < KDIM; k += 32) m = fmaxf(m, endW[k]);
            #pragma unroll
            for (int o = 16; o; o >>= 1) m = fmaxf(m, __shfl_xor_sync(F, m, o));
            float s = 0.f;
            for (int k = tid; k < KDIM; k += 32) s += __expf(endW[k] - m);
            #pragma unroll
            for (int o = 16; o; o >>= 1) s += __shfl_xor_sync(F, s, o);
            float lse = m + __logf(s);
            for (int k = tid; k < KDIM; k += 32) g_logE[k] = endW[k] - lse;
        }
        __syncthreads();
        __threadfence();
        if (tid == 0) atomicAdd(&g_done, 1);
    }

    // ---- Prologue: pack group 0 -> buffer 0 ----
    #pragma unroll 1
    for (int r = 0; r < 4; ++r) {
        int row_local = w * 4 + r;
        const int4* __restrict__ xr =
            (const int4*)(x + (size_t)(r0 + row_local) * NSTEPS);
        int4 q[4];
        load_row(xr, lane, q);
        process_store_row(q, lane, s_words[0][row_local], s_ps[0][row_local]);
    }
    __syncthreads();

    // ---- Barrier: wait for table completion ----
    if (tid == 0) {
        while (atomicAdd(&g_done, 0) < PREP_TOTAL) __nanosleep(64);
    }
    __syncthreads();
    __threadfence();

    const __half* __restrict__ T = g_T4 + (size_t)(w * 16) * 8192;

    // ---- Iter 0: walk group 0, interleaved with load+pack of group 1 ----
    {
        int p = s_ps[0][lane][w];
        uint64_t word = (uint64_t)s_words[0][lane][2 * w + 0]
                      | ((uint64_t)s_words[0][lane][2 * w + 1] << 32);
        unsigned hq = (unsigned)p << 4;
        float acc0 = 0.f, acc1 = 0.f;

        #pragma unroll
        for (int r = 0; r < 4; ++r) {
            // issue next-group x loads for this warp's row r
            const int4* __restrict__ xr = (const int4*)
                (x + (size_t)(r0 + RPG + w * 4 + r) * NSTEPS);
            int4 q[4];
            load_row(xr, lane, q);

            // 4 table gathers of the current group (overlap the x loads)
            #pragma unroll
            for (int kk = 0; kk < 4; ++kk) {
                int k = r * 4 + kk;
                unsigned c = (unsigned)(word >> (4 * k)) & 15u;
                float v = __half2float(__ldg(&T[k * 8192 + (hq | c)]));
                if (k & 1) acc1 += v; else acc0 += v;
                hq += (unsigned)__popc(c) << 4;
            }

            // consume the x data (ballot/shuffle pack) -> buffer 1
            process_store_row(q, lane, s_words[1][w * 4 + r],
                              s_ps[1][w * 4 + r]);
        }

        float acc = acc0 + acc1;
        if (w == NSEG - 1) acc += g_logE[hq >> 4];
        s_part[0][w][lane] = acc;
    }
    __syncthreads();

    if (w == 0) {
        float s = 0.f;
        #pragma unroll
        for (int j = 0; j < NSEG; ++j) s += s_part[0][j][lane];
        out[r0 + lane] = s;
    }

    // ---- Iter 1: walk group 1 (tail, no pack to overlap) ----
    {
        int p = s_ps[1][lane][w];
        uint64_t word = (uint64_t)s_words[1][lane][2 * w + 0]
                      | ((uint64_t)s_words[1][lane][2 * w + 1] << 32);
        unsigned hq = (unsigned)p << 4;
        float acc0 = 0.f, acc1 = 0.f;

        #pragma unroll
        for (int k = 0; k < 16; ++k) {
            unsigned c = (unsigned)(word >> (4 * k)) & 15u;
            float v = __half2float(__ldg(&T[k * 8192 + (hq | c)]));
            if (k & 1) acc1 += v; else acc0 += v;
            hq += (unsigned)__popc(c) << 4;
        }

        float acc = acc0 + acc1;
        if (w == NSEG - 1) acc += g_logE[hq >> 4];
        s_part[1][w][lane] = acc;
    }
    __syncthreads();

    if (w == 0) {
        float s = 0.f;
        #pragma unroll
        for (int j = 0; j < NSEG; ++j) s += s_part[1][j][lane];
        out[r0 + RPG + lane] = s;
    }

    // ---- Reset barrier state for the next graph replay (deterministic) ----
    if (tid == 0) {
        int f = atomicAdd(&g_fin, 1);
        if (f == (int)gridDim.x - 1) {
            g_done = 0;
            __threadfence();
            g_fin = 0;
        }
    }
}

// ---------------------------------------------------------------------------
extern "C" void kernel_launch(void* const* d_in, const int* in_sizes, int n_in,
                              void* d_out, int out_size) {
    const int*   x    = (const int*)  d_in[0];   // (65536, 512) int32
    const float* W    = (const float*)d_in[1];   // (511, 512, 2) float32
    const float* endW = (const float*)d_in[2];   // (1, 513) float32
    float* out = (float*)d_out;

    (void)in_sizes; (void)n_in; (void)out_size;

    mega_kernel<<<BATCH / RPB, NTHR>>>(x, W, endW, out);
}